// round 10
// baseline (speedup 1.0000x reference)
#include <cuda_runtime.h>
#include <math.h>

// ---------------- grid config ----------------
#define G 40
#define G3 (G * G * G)
#define ORG (-5.0f)
#define H 0.25f
#define INVH 4.0f
#define MAXP 16384

// ---------------- device scratch ----------------
// g_cnt must be zero at kernel_launch entry: zero-initialized at load,
// and k_scatter re-zeroes it every call (invariant across graph replays).
__device__ int    g_cnt[2][G3];
__device__ int    g_start[2][G3 + 1];
__device__ int    g_cur[2][G3];
__device__ float4 g_pts[2][MAXP];   // grid-sorted points
__device__ int    g_orig[2][MAXP];  // original index of sorted point
__device__ float  g_dist[2][MAXP];  // nearest distance per ORIGINAL index

__device__ __forceinline__ int cellco(float x) {
    int c = (int)floorf((x - ORG) * INVH);
    return min(G - 1, max(0, c));
}

// ---------------- kernel 1: histogram ----------------
__global__ void k_hist(const float* __restrict__ tp, const float* __restrict__ pp,
                       int N, int M) {
    int d = blockIdx.y;
    const float* __restrict__ P = d ? pp : tp;
    int n = d ? M : N;
    int i = blockIdx.x * 256 + threadIdx.x;
    if (i < n) {
        int cx = cellco(P[3 * i + 0]);
        int cy = cellco(P[3 * i + 1]);
        int cz = cellco(P[3 * i + 2]);
        atomicAdd(&g_cnt[d][(cz * G + cy) * G + cx], 1);
    }
}

// ---------------- kernel 2: exclusive prefix sum (one block per dir) ----------------
#define SCAN_T 1024
#define CH ((G3 + SCAN_T - 1) / SCAN_T)   // 63
__global__ void k_scan() {
    __shared__ int sm[SCAN_T];
    int d = blockIdx.x;
    int t = threadIdx.x;
    int base = t * CH;
    int s = 0;
    for (int i = 0; i < CH; i++) {
        int c = base + i;
        if (c < G3) s += g_cnt[d][c];
    }
    sm[t] = s;
    __syncthreads();
    for (int off = 1; off < SCAN_T; off <<= 1) {
        int v = (t >= off) ? sm[t - off] : 0;
        __syncthreads();
        sm[t] += v;
        __syncthreads();
    }
    int run = sm[t] - s;  // exclusive base for this chunk
    for (int i = 0; i < CH; i++) {
        int c = base + i;
        if (c < G3) {
            int cnt = g_cnt[d][c];
            g_start[d][c] = run;
            g_cur[d][c] = run;
            run += cnt;
        }
    }
    if (t == SCAN_T - 1) g_start[d][G3] = run;
}

// ---------------- kernel 3: scatter into grid order + re-zero counts ----------------
__global__ void k_scatter(const float* __restrict__ tp, const float* __restrict__ pp,
                          int N, int M) {
    int d = blockIdx.y;
    const float* __restrict__ P = d ? pp : tp;
    int n = d ? M : N;
    int i = blockIdx.x * 256 + threadIdx.x;
    if (i < n) {
        float x = P[3 * i + 0], y = P[3 * i + 1], z = P[3 * i + 2];
        int c = (cellco(z) * G + cellco(y)) * G + cellco(x);
        int slot = atomicAdd(&g_cur[d][c], 1);
        g_pts[d][slot] = make_float4(x, y, z, 0.f);
        g_orig[d][slot] = i;
    }
    // re-zero counts for the next graph replay (invariant: zero at entry)
    int nthread = gridDim.x * 256;
    for (int c = blockIdx.x * 256 + threadIdx.x; c < G3; c += nthread)
        g_cnt[d][c] = 0;
}

// ---------------- kernel 4: exact NN via ring search ----------------
__global__ void k_query(int N, int M, float* __restrict__ out) {
    int d = blockIdx.y;           // query set
    int s = 1 - d;                // searched set
    int n = d ? M : N;
    int j = blockIdx.x * 128 + threadIdx.x;
    if (j >= n) return;

    float4 q = g_pts[d][j];       // sorted order -> warp-coherent cells
    int orig = g_orig[d][j];
    int cx = cellco(q.x), cy = cellco(q.y), cz = cellco(q.z);

    float best = 3e38f;
    for (int k = 1; k <= G; k++) {
        int zlo = max(cz - k, 0), zhi = min(cz + k, G - 1);
        int ylo = max(cy - k, 0), yhi = min(cy + k, G - 1);
        int xlo = max(cx - k, 0), xhi = min(cx + k, G - 1);
        for (int z = zlo; z <= zhi; z++) {
            int adz = (z > cz) ? (z - cz) : (cz - z);
            for (int y = ylo; y <= yhi; y++) {
                int ady = (y > cy) ? (y - cy) : (cy - y);
                int rowbase = (z * G + y) * G;
                int s0, s1;
                if (k == 1 || adz == k || ady == k) {
                    // whole row is new: contiguous candidate span
                    s0 = g_start[s][rowbase + xlo];
                    s1 = g_start[s][rowbase + xhi + 1];
                    for (int i = s0; i < s1; i++) {
                        float4 p = g_pts[s][i];
                        float dx = q.x - p.x, dy = q.y - p.y, dz = q.z - p.z;
                        float dd = fmaf(dx, dx, fmaf(dy, dy, dz * dz));
                        best = fminf(best, dd);
                    }
                } else {
                    // only x = cx-k and cx+k are new
                    int xa = cx - k;
                    if (xa >= 0) {
                        s0 = g_start[s][rowbase + xa];
                        s1 = g_start[s][rowbase + xa + 1];
                        for (int i = s0; i < s1; i++) {
                            float4 p = g_pts[s][i];
                            float dx = q.x - p.x, dy = q.y - p.y, dz = q.z - p.z;
                            float dd = fmaf(dx, dx, fmaf(dy, dy, dz * dz));
                            best = fminf(best, dd);
                        }
                    }
                    int xb = cx + k;
                    if (xb <= G - 1) {
                        s0 = g_start[s][rowbase + xb];
                        s1 = g_start[s][rowbase + xb + 1];
                        for (int i = s0; i < s1; i++) {
                            float4 p = g_pts[s][i];
                            float dx = q.x - p.x, dy = q.y - p.y, dz = q.z - p.z;
                            float dd = fmaf(dx, dx, fmaf(dy, dy, dz * dz));
                            best = fminf(best, dd);
                        }
                    }
                }
            }
        }
        // termination: full grid searched?
        bool coverall = (cx - k <= 0) && (cx + k >= G - 1) &&
                        (cy - k <= 0) && (cy + k >= G - 1) &&
                        (cz - k <= 0) && (cz + k >= G - 1);
        if (coverall) break;
        // distance from q to nearest unsearched cell region (grid-edge faces = inf)
        float dbx = fminf((cx - k <= 0)     ? 3e38f : q.x - (ORG + (cx - k) * H),
                          (cx + k >= G - 1) ? 3e38f : (ORG + (cx + k + 1) * H) - q.x);
        float dby = fminf((cy - k <= 0)     ? 3e38f : q.y - (ORG + (cy - k) * H),
                          (cy + k >= G - 1) ? 3e38f : (ORG + (cy + k + 1) * H) - q.y);
        float dbz = fminf((cz - k <= 0)     ? 3e38f : q.z - (ORG + (cz - k) * H),
                          (cz + k >= G - 1) ? 3e38f : (ORG + (cz + k + 1) * H) - q.z);
        float db = fminf(dbx, fminf(dby, dbz));
        if (db >= 0.f && best <= db * db) break;
    }

    float dist = sqrtf(best);
    g_dist[d][orig] = dist;
    if (d == 1) out[1 + orig] = dist;   // mins_seeds
}

// ---------------- kernel 5: deterministic final sums + scalars ----------------
__global__ void k_out(int N, int M, float* __restrict__ out) {
    __shared__ float sm0[1024], sm1[1024];
    int t = threadIdx.x;
    float s0 = 0.f, s1 = 0.f;
    for (int i = t; i < N; i += 1024) s0 += g_dist[0][i];
    for (int i = t; i < M; i += 1024) s1 += g_dist[1][i];
    sm0[t] = s0; sm1[t] = s1;
    __syncthreads();
    for (int st = 512; st > 0; st >>= 1) {
        if (t < st) { sm0[t] += sm0[t + st]; sm1[t] += sm1[t + st]; }
        __syncthreads();
    }
    if (t == 0) {
        float loss = sm0[0] / (float)N;        // mean(mins)
        float loss_seeds = sm1[0] / (float)M;  // mean(mins_seeds)
        out[0] = loss + loss_seeds;
        out[1 + M] = loss;
        out[2 + M] = loss_seeds;
    }
}

// ---------------- launch ----------------
extern "C" void kernel_launch(void* const* d_in, const int* in_sizes, int n_in,
                              void* d_out, int out_size) {
    const float* tp = (const float*)d_in[0];
    const float* pp = (const float*)d_in[1];
    float* out = (float*)d_out;
    const int N = in_sizes[0] / 3;
    const int M = in_sizes[1] / 3;
    const int maxP = (N > M) ? N : M;

    dim3 gh((maxP + 255) / 256, 2);
    k_hist<<<gh, 256>>>(tp, pp, N, M);

    k_scan<<<2, SCAN_T>>>();

    k_scatter<<<gh, 256>>>(tp, pp, N, M);

    dim3 gq((maxP + 127) / 128, 2);
    k_query<<<gq, 128>>>(N, M, out);

    k_out<<<1, 1024>>>(N, M, out);
}

// round 11
// speedup vs baseline: 3.0933x; 3.0933x over previous
#include <cuda_runtime.h>
#include <math.h>

// ---------------- grid config ----------------
#define G 20
#define G3 (G * G * G)          // 8000 cells
#define ORG (-5.0f)
#define H 0.5f
#define INVH 2.0f
#define MAXP 16384

// ---------------- device scratch ----------------
// g_cnt must be zero at entry: zero-initialized at load; k_scatter re-zeroes
// it every call (invariant preserved across graph replays).
__device__ int    g_cnt[2][G3];
__device__ int    g_start[2][G3 + 1];
__device__ int    g_cur[2][G3];
__device__ float4 g_pts[2][MAXP];   // grid-sorted points
__device__ int    g_orig[2][MAXP];  // original index of sorted point
__device__ float  g_dist[2][MAXP];  // nearest distance per ORIGINAL index

__device__ __forceinline__ int cellco(float x) {
    int c = (int)floorf((x - ORG) * INVH);
    return min(G - 1, max(0, c));
}
__device__ __forceinline__ unsigned redux_min_u32(unsigned v) {
    unsigned d;
    asm("redux.sync.min.u32 %0, %1, 0xFFFFFFFF;" : "=r"(d) : "r"(v));
    return d;
}

// ---------------- kernel 1: histogram ----------------
__global__ void k_hist(const float* __restrict__ tp, const float* __restrict__ pp,
                       int N, int M) {
    int d = blockIdx.y;
    const float* __restrict__ P = d ? pp : tp;
    int n = d ? M : N;
    int i = blockIdx.x * 256 + threadIdx.x;
    if (i < n) {
        int cx = cellco(P[3 * i + 0]);
        int cy = cellco(P[3 * i + 1]);
        int cz = cellco(P[3 * i + 2]);
        atomicAdd(&g_cnt[d][(cz * G + cy) * G + cx], 1);
    }
}

// ---------------- kernel 2: exclusive prefix sum (one block per dir) ----------------
#define SCAN_T 1024
#define CH 8   // 1024*8 = 8192 >= 8000
__global__ void k_scan() {
    __shared__ int sm[SCAN_T];
    int d = blockIdx.x;
    int t = threadIdx.x;
    int base = t * CH;
    int s = 0;
    #pragma unroll
    for (int i = 0; i < CH; i++) {
        int c = base + i;
        if (c < G3) s += g_cnt[d][c];
    }
    sm[t] = s;
    __syncthreads();
    for (int off = 1; off < SCAN_T; off <<= 1) {
        int v = (t >= off) ? sm[t - off] : 0;
        __syncthreads();
        sm[t] += v;
        __syncthreads();
    }
    int run = sm[t] - s;  // exclusive base for this chunk
    #pragma unroll
    for (int i = 0; i < CH; i++) {
        int c = base + i;
        if (c < G3) {
            int cnt = g_cnt[d][c];
            g_start[d][c] = run;
            g_cur[d][c] = run;
            run += cnt;
        }
    }
    if (t == SCAN_T - 1) g_start[d][G3] = run;
}

// ---------------- kernel 3: scatter into grid order + re-zero counts ----------------
__global__ void k_scatter(const float* __restrict__ tp, const float* __restrict__ pp,
                          int N, int M) {
    int d = blockIdx.y;
    const float* __restrict__ P = d ? pp : tp;
    int n = d ? M : N;
    int i = blockIdx.x * 256 + threadIdx.x;
    if (i < n) {
        float x = P[3 * i + 0], y = P[3 * i + 1], z = P[3 * i + 2];
        int c = (cellco(z) * G + cellco(y)) * G + cellco(x);
        int slot = atomicAdd(&g_cur[d][c], 1);
        g_pts[d][slot] = make_float4(x, y, z, 0.f);
        g_orig[d][slot] = i;
    }
    // re-zero counts for the next graph replay
    int nthread = gridDim.x * 256;
    for (int c = blockIdx.x * 256 + threadIdx.x; c < G3; c += nthread)
        g_cnt[d][c] = 0;
}

// ---------------- kernel 4: exact NN, WARP per query ----------------
#define QW 8   // warps per block
__global__ void __launch_bounds__(QW * 32)
k_query(int N, int M, float* __restrict__ out) {
    const int wg = blockIdx.x * QW + (threadIdx.x >> 5);
    const int lane = threadIdx.x & 31;
    const int total = N + M;
    if (wg >= total) return;          // whole warp exits together
    const int d = (wg >= N) ? 1 : 0;  // query set
    const int j = d ? (wg - N) : wg;
    const int s = 1 - d;              // searched set

    const float4 q = g_pts[d][j];     // sorted order -> warp-coherent cells
    const int cx = cellco(q.x), cy = cellco(q.y), cz = cellco(q.z);

    float best = 3e38f;               // lane-partial min of d^2
    for (int k = 1; k <= G; k++) {
        int zlo = max(cz - k, 0), zhi = min(cz + k, G - 1);
        int ylo = max(cy - k, 0), yhi = min(cy + k, G - 1);
        int xlo = max(cx - k, 0), xhi = min(cx + k, G - 1);
        for (int z = zlo; z <= zhi; z++) {
            int adz = (z > cz) ? (z - cz) : (cz - z);
            for (int y = ylo; y <= yhi; y++) {
                int ady = (y > cy) ? (y - cy) : (cy - y);
                int rowbase = (z * G + y) * G;
                if (k == 1 || adz == k || ady == k) {
                    // whole row new: one contiguous span, lanes stride it
                    int s0 = g_start[s][rowbase + xlo];
                    int s1 = g_start[s][rowbase + xhi + 1];
                    for (int i = s0 + lane; i < s1; i += 32) {
                        float4 p = g_pts[s][i];
                        float dx = q.x - p.x, dy = q.y - p.y, dz = q.z - p.z;
                        best = fminf(best, fmaf(dx, dx, fmaf(dy, dy, dz * dz)));
                    }
                } else {
                    // only x = cx-k and cx+k are new
                    int xa = cx - k;
                    if (xa >= 0) {
                        int s0 = g_start[s][rowbase + xa];
                        int s1 = g_start[s][rowbase + xa + 1];
                        for (int i = s0 + lane; i < s1; i += 32) {
                            float4 p = g_pts[s][i];
                            float dx = q.x - p.x, dy = q.y - p.y, dz = q.z - p.z;
                            best = fminf(best, fmaf(dx, dx, fmaf(dy, dy, dz * dz)));
                        }
                    }
                    int xb = cx + k;
                    if (xb <= G - 1) {
                        int s0 = g_start[s][rowbase + xb];
                        int s1 = g_start[s][rowbase + xb + 1];
                        for (int i = s0 + lane; i < s1; i += 32) {
                            float4 p = g_pts[s][i];
                            float dx = q.x - p.x, dy = q.y - p.y, dz = q.z - p.z;
                            best = fminf(best, fmaf(dx, dx, fmaf(dy, dy, dz * dz)));
                        }
                    }
                }
            }
        }
        // warp-combine (d^2 >= 0 -> uint order == float order)
        best = __uint_as_float(redux_min_u32(__float_as_uint(best)));

        bool coverall = (cx - k <= 0) && (cx + k >= G - 1) &&
                        (cy - k <= 0) && (cy + k >= G - 1) &&
                        (cz - k <= 0) && (cz + k >= G - 1);
        if (coverall) break;
        // distance from q to nearest unsearched region (grid-edge faces = inf)
        float dbx = fminf((cx - k <= 0)     ? 3e38f : q.x - (ORG + (cx - k) * H),
                          (cx + k >= G - 1) ? 3e38f : (ORG + (cx + k + 1) * H) - q.x);
        float dby = fminf((cy - k <= 0)     ? 3e38f : q.y - (ORG + (cy - k) * H),
                          (cy + k >= G - 1) ? 3e38f : (ORG + (cy + k + 1) * H) - q.y);
        float dbz = fminf((cz - k <= 0)     ? 3e38f : q.z - (ORG + (cz - k) * H),
                          (cz + k >= G - 1) ? 3e38f : (ORG + (cz + k + 1) * H) - q.z);
        float db = fminf(dbx, fminf(dby, dbz));
        if (db >= 0.f && best <= db * db) break;
    }

    if (lane == 0) {
        int orig = g_orig[d][j];
        float dist = sqrtf(best);
        g_dist[d][orig] = dist;
        if (d == 1) out[1 + orig] = dist;   // mins_seeds
    }
}

// ---------------- kernel 5: deterministic final sums + scalars ----------------
__global__ void k_out(int N, int M, float* __restrict__ out) {
    __shared__ float sm0[1024], sm1[1024];
    int t = threadIdx.x;
    float s0 = 0.f, s1 = 0.f;
    for (int i = t; i < N; i += 1024) s0 += g_dist[0][i];
    for (int i = t; i < M; i += 1024) s1 += g_dist[1][i];
    sm0[t] = s0; sm1[t] = s1;
    __syncthreads();
    for (int st = 512; st > 0; st >>= 1) {
        if (t < st) { sm0[t] += sm0[t + st]; sm1[t] += sm1[t + st]; }
        __syncthreads();
    }
    if (t == 0) {
        float loss = sm0[0] / (float)N;        // mean(mins)
        float loss_seeds = sm1[0] / (float)M;  // mean(mins_seeds)
        out[0] = loss + loss_seeds;
        out[1 + M] = loss;
        out[2 + M] = loss_seeds;
    }
}

// ---------------- launch ----------------
extern "C" void kernel_launch(void* const* d_in, const int* in_sizes, int n_in,
                              void* d_out, int out_size) {
    const float* tp = (const float*)d_in[0];
    const float* pp = (const float*)d_in[1];
    float* out = (float*)d_out;
    const int N = in_sizes[0] / 3;
    const int M = in_sizes[1] / 3;
    const int maxP = (N > M) ? N : M;

    dim3 gh((maxP + 255) / 256, 2);
    k_hist<<<gh, 256>>>(tp, pp, N, M);

    k_scan<<<2, SCAN_T>>>();

    k_scatter<<<gh, 256>>>(tp, pp, N, M);

    const int totalq = N + M;
    const int qblocks = (totalq + QW - 1) / QW;   // 3072 blocks of 8 warps
    k_query<<<qblocks, QW * 32>>>(N, M, out);

    k_out<<<1, 1024>>>(N, M, out);
}